// round 7
// baseline (speedup 1.0000x reference)
#include <cuda_runtime.h>
#include <cstdint>

#define NNODES 20000
#define NEDGES 320000
#define DIM    512

// Scratch (allocation-free rule: __device__ globals)
__device__ float g_h[(size_t)NNODES * DIM];   // GEMM output h = x @ W
__device__ float g_a[(size_t)NNODES * DIM];   // layer-1 aggregation result
__device__ float g_dinv[NNODES];
__device__ int   g_deg[NNODES];
__device__ int   g_src[NEDGES];
__device__ int   g_dst[NEDGES];
__device__ int   g_is_i32;            // nonzero -> edge_index buffer is int32
__device__ int   g_rowptr[NNODES + 1];
__device__ int   g_cursor[NNODES];
__device__ int   g_csr_src[NEDGES];
__device__ float g_csr_w[NEDGES];
__device__ float g_w1t[DIM * DIM];    // W1^T, pre-converted to tf32 bits
__device__ float g_w2t[DIM * DIM];    // W2^T, pre-converted to tf32 bits

__device__ __forceinline__ uint32_t f2tf32(float f) {
    uint32_t r;
    asm("cvt.rna.tf32.f32 %0, %1;" : "=r"(r) : "f"(f));
    return r;
}

// ---------------------------------------------------------------------------
// Prep: flag+degree init
// ---------------------------------------------------------------------------
__global__ void init_kernel() {
    int i = blockIdx.x * blockDim.x + threadIdx.x;
    if (i == 0) g_is_i32 = 0;
    if (i < NNODES) g_deg[i] = 1;  // self-loop
}

__global__ void dtype_sniff_kernel(const int* __restrict__ ei32) {
    int i = blockIdx.x * blockDim.x + threadIdx.x;  // 0 .. E-1
    int acc = 0;
    if (i < NEDGES) acc = ei32[2 * i + 1];
#pragma unroll
    for (int o = 16; o > 0; o >>= 1) acc |= __shfl_xor_sync(0xffffffffu, acc, o);
    if ((threadIdx.x & 31) == 0 && acc != 0) atomicOr(&g_is_i32, 1);
}

// convert edge index to int32 AND count in-degree in one pass
__global__ void convert_count_kernel(const void* __restrict__ ei) {
    int i = blockIdx.x * blockDim.x + threadIdx.x;  // 0 .. 2E-1
    if (i >= 2 * NEDGES) return;
    int v;
    if (g_is_i32) v = ((const int*)ei)[i];
    else          v = (int)((const long long*)ei)[i];
    if (i < NEDGES) {
        g_src[i] = v;
    } else {
        g_dst[i - NEDGES] = v;
        atomicAdd(&g_deg[v], 1);
    }
}

__global__ void dinv_kernel() {
    int i = blockIdx.x * blockDim.x + threadIdx.x;
    if (i < NNODES) g_dinv[i] = rsqrtf((float)g_deg[i]);
}

// ---------------------------------------------------------------------------
// Exclusive prefix scan of in-degree (deg-1) -> rowptr, cursor. 1 block.
// ---------------------------------------------------------------------------
#define SCAN_T 1024
__global__ void scan_kernel() {
    __shared__ int sums[SCAN_T];
    const int CH = (NNODES + SCAN_T - 1) / SCAN_T;  // 20
    int t = threadIdx.x;
    int base = t * CH;
    int local = 0;
#pragma unroll
    for (int i = 0; i < CH; i++) {
        int idx = base + i;
        if (idx < NNODES) local += g_deg[idx] - 1;
    }
    sums[t] = local;
    __syncthreads();
    for (int o = 1; o < SCAN_T; o <<= 1) {
        int v = (t >= o) ? sums[t - o] : 0;
        __syncthreads();
        sums[t] += v;
        __syncthreads();
    }
    int run = (t > 0) ? sums[t - 1] : 0;
#pragma unroll
    for (int i = 0; i < CH; i++) {
        int idx = base + i;
        if (idx < NNODES) {
            g_rowptr[idx] = run;
            g_cursor[idx] = run;
            run += g_deg[idx] - 1;
        }
    }
    if (t == SCAN_T - 1) g_rowptr[NNODES] = sums[SCAN_T - 1];
}

__global__ void scatter_kernel() {
    int e = blockIdx.x * blockDim.x + threadIdx.x;
    if (e >= NEDGES) return;
    int s = g_src[e];
    int d = g_dst[e];
    int pos = atomicAdd(&g_cursor[d], 1);
    g_csr_src[pos] = s;
    g_csr_w[pos] = g_dinv[s] * g_dinv[d];
}

// ---------------------------------------------------------------------------
// Transpose 512x512 W -> Wt with tf32 pre-conversion. blockIdx.z: 0=W1, 1=W2
// ---------------------------------------------------------------------------
__global__ void transpose512_kernel(const float* __restrict__ W1,
                                    const float* __restrict__ W2) {
    __shared__ float t[32][33];
    const float* W = blockIdx.z ? W2 : W1;
    float* o = blockIdx.z ? g_w2t : g_w1t;
    int bx = blockIdx.x * 32, by = blockIdx.y * 32;
    t[threadIdx.y][threadIdx.x] = W[(by + threadIdx.y) * DIM + bx + threadIdx.x];
    __syncthreads();
    o[(bx + threadIdx.y) * DIM + by + threadIdx.x] =
        __uint_as_float(f2tf32(t[threadIdx.x][threadIdx.y]));
}

// ---------------------------------------------------------------------------
// Pipelined tensor-core GEMM via mma.sync tf32:
//   g_h[M,512] = op(A)[M,512] @ W[512,512]
//   MODE 0: A = Aparam (raw),     B = g_w1t (tf32 bits)
//   MODE 1: A = relu(g_a + bias), B = g_w2t (tf32 bits)
// CTA 128x128, BK=32, 256 threads = 8 warps (4 M x 2 N), warp tile 32x64.
// Double-buffered SMEM (72KB dynamic), reg-staged prefetch of chunk c+1
// interleaved with the MMAs of chunk c.
// ---------------------------------------------------------------------------
#define SMS 36                        // smem row stride (32 + 4 pad)
#define SM_BUF (128 * SMS)            // words per tile buffer
#define GEMM_SMEM_BYTES (4 * SM_BUF * 4)  // A0,B0,A1,B1

template <int MODE>
__device__ __forceinline__ void load_tileA(float4 (&st)[4], const float* __restrict__ A,
                                           int row0, int kc, int tid, float4 bb) {
#pragma unroll
    for (int i = 0; i < 4; i++) {
        int idx = tid + 256 * i;
        int r = idx >> 3, c4 = idx & 7;
        int grow = row0 + r;
        float4 v = make_float4(0.f, 0.f, 0.f, 0.f);
        if (grow < NNODES)
            v = *(const float4*)&A[(size_t)grow * DIM + kc + c4 * 4];
        if (MODE == 1) {
            v.x = fmaxf(v.x + bb.x, 0.f);
            v.y = fmaxf(v.y + bb.y, 0.f);
            v.z = fmaxf(v.z + bb.z, 0.f);
            v.w = fmaxf(v.w + bb.w, 0.f);
        }
        st[i] = v;
    }
}

__device__ __forceinline__ void store_tileA(uint32_t* buf, const float4 (&st)[4], int tid) {
#pragma unroll
    for (int i = 0; i < 4; i++) {
        int idx = tid + 256 * i;
        int r = idx >> 3, c4 = idx & 7;
        *(uint4*)&buf[r * SMS + c4 * 4] =
            make_uint4(f2tf32(st[i].x), f2tf32(st[i].y), f2tf32(st[i].z), f2tf32(st[i].w));
    }
}

__device__ __forceinline__ void load_tileB(float4 (&st)[4], const float* __restrict__ Bt,
                                           int col0, int kc, int tid) {
#pragma unroll
    for (int i = 0; i < 4; i++) {
        int idx = tid + 256 * i;
        int r = idx >> 3, c4 = idx & 7;
        st[i] = *(const float4*)&Bt[(size_t)(col0 + r) * DIM + kc + c4 * 4];
    }
}

__device__ __forceinline__ void store_tileB(uint32_t* buf, const float4 (&st)[4], int tid) {
#pragma unroll
    for (int i = 0; i < 4; i++) {
        int idx = tid + 256 * i;
        int r = idx >> 3, c4 = idx & 7;
        *(uint4*)&buf[r * SMS + c4 * 4] =
            make_uint4(__float_as_uint(st[i].x), __float_as_uint(st[i].y),
                       __float_as_uint(st[i].z), __float_as_uint(st[i].w));
    }
}

__device__ __forceinline__ void mma_ks(const uint32_t* __restrict__ As_,
                                       const uint32_t* __restrict__ Bs_,
                                       float (&acc)[2][8][4],
                                       int k0, int wm, int wn, int gq, int tq) {
    uint32_t af[2][4], bf[8][2];
#pragma unroll
    for (int mt = 0; mt < 2; mt++) {
        int r = wm + mt * 16 + gq;
        af[mt][0] = As_[r * SMS + k0 + tq];
        af[mt][1] = As_[(r + 8) * SMS + k0 + tq];
        af[mt][2] = As_[r * SMS + k0 + tq + 4];
        af[mt][3] = As_[(r + 8) * SMS + k0 + tq + 4];
    }
#pragma unroll
    for (int nt = 0; nt < 8; nt++) {
        int n = wn + nt * 8 + gq;
        bf[nt][0] = Bs_[n * SMS + k0 + tq];
        bf[nt][1] = Bs_[n * SMS + k0 + tq + 4];
    }
#pragma unroll
    for (int mt = 0; mt < 2; mt++)
#pragma unroll
        for (int nt = 0; nt < 8; nt++) {
            asm volatile(
                "mma.sync.aligned.m16n8k8.row.col.f32.tf32.tf32.f32 "
                "{%0,%1,%2,%3}, {%4,%5,%6,%7}, {%8,%9}, {%0,%1,%2,%3};"
                : "+f"(acc[mt][nt][0]), "+f"(acc[mt][nt][1]),
                  "+f"(acc[mt][nt][2]), "+f"(acc[mt][nt][3])
                : "r"(af[mt][0]), "r"(af[mt][1]),
                  "r"(af[mt][2]), "r"(af[mt][3]),
                  "r"(bf[nt][0]), "r"(bf[nt][1]));
        }
}

template <int MODE>
__global__ void __launch_bounds__(256)
mma_gemm_kernel(const float* __restrict__ Aparam, const float* __restrict__ bias) {
    extern __shared__ uint32_t smem[];  // [A0 | B0 | A1 | B1], SM_BUF words each

    const float* A  = (MODE == 0) ? Aparam : g_a;
    const float* Bt = (MODE == 0) ? g_w1t : g_w2t;

    int tid = threadIdx.x, wid = tid >> 5, lane = tid & 31;
    int row0 = blockIdx.y * 128;
    int col0 = blockIdx.x * 128;
    int wm = (wid & 3) * 32;
    int wn = (wid >> 2) * 64;
    int gq = lane >> 2;
    int tq = lane & 3;

    float acc[2][8][4];
#pragma unroll
    for (int mt = 0; mt < 2; mt++)
#pragma unroll
        for (int nt = 0; nt < 8; nt++)
#pragma unroll
            for (int j = 0; j < 4; j++) acc[mt][nt][j] = 0.f;

    float4 stg[4];

    // prologue: chunk 0 -> buffers 0
    float4 bb = make_float4(0.f, 0.f, 0.f, 0.f);
    if (MODE == 1) bb = *(const float4*)&bias[(tid & 7) * 4];
    load_tileA<MODE>(stg, A, row0, 0, tid, bb);
    store_tileA(smem, stg, tid);
    load_tileB(stg, Bt, col0, 0, tid);
    store_tileB(smem + SM_BUF, stg, tid);
    __syncthreads();

    for (int c = 0; c < 16; c++) {
        uint32_t* curA = smem + (c & 1) * 2 * SM_BUF;
        uint32_t* curB = curA + SM_BUF;
        uint32_t* nxtA = smem + ((c + 1) & 1) * 2 * SM_BUF;
        uint32_t* nxtB = nxtA + SM_BUF;
        bool pre = (c < 15);
        int kn = (c + 1) * 32;

        if (pre) {
            if (MODE == 1) bb = *(const float4*)&bias[kn + (tid & 7) * 4];
            load_tileA<MODE>(stg, A, row0, kn, tid, bb);
        }
        mma_ks(curA, curB, acc, 0, wm, wn, gq, tq);
        mma_ks(curA, curB, acc, 8, wm, wn, gq, tq);
        if (pre) {
            store_tileA(nxtA, stg, tid);
            load_tileB(stg, Bt, col0, kn, tid);
        }
        mma_ks(curA, curB, acc, 16, wm, wn, gq, tq);
        mma_ks(curA, curB, acc, 24, wm, wn, gq, tq);
        if (pre) store_tileB(nxtB, stg, tid);
        __syncthreads();
    }

    // ---- epilogue: fragments -> g_h ----
#pragma unroll
    for (int mt = 0; mt < 2; mt++) {
        int r0 = row0 + wm + mt * 16 + gq;
#pragma unroll
        for (int nt = 0; nt < 8; nt++) {
            int cc = col0 + wn + nt * 8 + tq * 2;
            if (r0 < NNODES)
                *(float2*)&g_h[(size_t)r0 * DIM + cc] =
                    make_float2(acc[mt][nt][0], acc[mt][nt][1]);
            if (r0 + 8 < NNODES)
                *(float2*)&g_h[(size_t)(r0 + 8) * DIM + cc] =
                    make_float2(acc[mt][nt][2], acc[mt][nt][3]);
        }
    }
}

// ---------------------------------------------------------------------------
// Shared edge-accumulate body:
//   acc = dinv[d]^2 * h[d,:] + sum_{e: dst=d} w_e * h[src_e,:]   (one float4 col)
// ---------------------------------------------------------------------------
__device__ __forceinline__ float4 agg_row(int d, int t) {
    const float4* __restrict__ h4 = (const float4*)g_h;
    float dv = g_dinv[d];
    float4 acc = h4[(size_t)d * 128 + t];
    float ws = dv * dv;
    acc.x *= ws; acc.y *= ws; acc.z *= ws; acc.w *= ws;

    int j   = g_rowptr[d];
    int end = g_rowptr[d + 1];
    for (; j + 4 <= end; j += 4) {
        int   s0 = g_csr_src[j],     s1 = g_csr_src[j + 1];
        int   s2 = g_csr_src[j + 2], s3 = g_csr_src[j + 3];
        float w0 = g_csr_w[j],       w1 = g_csr_w[j + 1];
        float w2 = g_csr_w[j + 2],   w3 = g_csr_w[j + 3];
        float4 v0 = h4[(size_t)s0 * 128 + t];
        float4 v1 = h4[(size_t)s1 * 128 + t];
        float4 v2 = h4[(size_t)s2 * 128 + t];
        float4 v3 = h4[(size_t)s3 * 128 + t];
        acc.x += v0.x * w0 + v1.x * w1 + v2.x * w2 + v3.x * w3;
        acc.y += v0.y * w0 + v1.y * w1 + v2.y * w2 + v3.y * w3;
        acc.z += v0.z * w0 + v1.z * w1 + v2.z * w2 + v3.z * w3;
        acc.w += v0.w * w0 + v1.w * w1 + v2.w * w2 + v3.w * w3;
    }
    for (; j < end; j++) {
        int   s = g_csr_src[j];
        float w = g_csr_w[j];
        float4 v = h4[(size_t)s * 128 + t];
        acc.x += v.x * w; acc.y += v.y * w;
        acc.z += v.z * w; acc.w += v.w * w;
    }
    return acc;
}

// Layer 1: store aggregation to g_a (consumed by GEMM 2 with bias+relu)
__global__ void __launch_bounds__(128)
agg_csr_kernel() {
    int d = blockIdx.x;
    int t = threadIdx.x;
    ((float4*)g_a)[(size_t)d * 128 + t] = agg_row(d, t);
}

// Layer 2: aggregation fused with bias + relu + global max pool.
// 8 nodes per block, running column-max in registers, 1 atomicMax/col/block.
#define NPB 8
__global__ void __launch_bounds__(128)
agg_pool_kernel(const float* __restrict__ b2, float* __restrict__ out) {
    int t = threadIdx.x;
    int d0 = blockIdx.x * NPB;
    float4 bb = ((const float4*)b2)[t];
    float4 mx = make_float4(0.f, 0.f, 0.f, 0.f);
#pragma unroll
    for (int n = 0; n < NPB; n++) {
        float4 acc = agg_row(d0 + n, t);
        mx.x = fmaxf(mx.x, acc.x + bb.x);
        mx.y = fmaxf(mx.y, acc.y + bb.y);
        mx.z = fmaxf(mx.z, acc.z + bb.z);
        mx.w = fmaxf(mx.w, acc.w + bb.w);
    }
    // relu floor is the 0-init of out; values >= 0 -> int compare OK
    mx.x = fmaxf(mx.x, 0.f); mx.y = fmaxf(mx.y, 0.f);
    mx.z = fmaxf(mx.z, 0.f); mx.w = fmaxf(mx.w, 0.f);
    int* o = (int*)out;
    atomicMax(o + 4 * t + 0, __float_as_int(mx.x));
    atomicMax(o + 4 * t + 1, __float_as_int(mx.y));
    atomicMax(o + 4 * t + 2, __float_as_int(mx.z));
    atomicMax(o + 4 * t + 3, __float_as_int(mx.w));
}

__global__ void out_init_kernel(float* out) {
    int j = threadIdx.x;
    if (j < DIM) out[j] = 0.0f;
}

// ---------------------------------------------------------------------------
extern "C" void kernel_launch(void* const* d_in, const int* in_sizes, int n_in,
                              void* d_out, int out_size) {
    const float* X  = (const float*)d_in[0];
    const void*  ei = d_in[1];
    // d_in[2] = edge_attr (unused by GCNConv)
    const float* W1 = (const float*)d_in[3];
    const float* b1 = (const float*)d_in[4];
    const float* W2 = (const float*)d_in[5];
    const float* b2 = (const float*)d_in[6];
    float* out = (float*)d_out;

    cudaFuncSetAttribute(mma_gemm_kernel<0>,
                         cudaFuncAttributeMaxDynamicSharedMemorySize, GEMM_SMEM_BYTES);
    cudaFuncSetAttribute(mma_gemm_kernel<1>,
                         cudaFuncAttributeMaxDynamicSharedMemorySize, GEMM_SMEM_BYTES);

    // ---- prep: edge dtype sniff/convert, degree, CSR, weight transposes ----
    init_kernel<<<(NNODES + 255) / 256, 256>>>();
    dtype_sniff_kernel<<<(NEDGES + 255) / 256, 256>>>((const int*)ei);
    convert_count_kernel<<<(2 * NEDGES + 255) / 256, 256>>>(ei);
    dinv_kernel<<<(NNODES + 255) / 256, 256>>>();
    scan_kernel<<<1, SCAN_T>>>();
    scatter_kernel<<<(NEDGES + 255) / 256, 256>>>();
    dim3 tgrid(16, 16, 2), tblk(32, 32);
    transpose512_kernel<<<tgrid, tblk>>>(W1, W2);
    out_init_kernel<<<1, DIM>>>(out);

    dim3 gemm_grid(DIM / 128, (NNODES + 127) / 128);  // (4, 157)

    // ---- layer 1: h = X @ W1 ; a = A_norm h ----
    mma_gemm_kernel<0><<<gemm_grid, 256, GEMM_SMEM_BYTES>>>(X, nullptr);
    agg_csr_kernel<<<NNODES, 128>>>();

    // ---- layer 2: h = relu(a + b1) @ W2 ; fused agg + relu + max pool ----
    mma_gemm_kernel<1><<<gemm_grid, 256, GEMM_SMEM_BYTES>>>(nullptr, b1);
    agg_pool_kernel<<<NNODES / NPB, 128>>>(b2, out);
}

// round 9
// speedup vs baseline: 1.0042x; 1.0042x over previous
#include <cuda_runtime.h>
#include <cstdint>

#define NNODES 20000
#define NEDGES 320000
#define DIM    512

// Scratch (allocation-free rule: __device__ globals)
__device__ float g_h[(size_t)NNODES * DIM];   // GEMM output h = x @ W
__device__ float g_a[(size_t)NNODES * DIM];   // GEMM A operand (tf32 bits)
__device__ float g_dinv[NNODES];
__device__ int   g_deg[NNODES];
__device__ int   g_src[NEDGES];
__device__ int   g_dst[NEDGES];
__device__ int   g_is_i32;            // nonzero -> edge_index buffer is int32
__device__ int   g_rowptr[NNODES + 1];
__device__ int   g_cursor[NNODES];
__device__ int   g_csr_src[NEDGES];
__device__ float g_csr_w[NEDGES];
__device__ float g_w1t[DIM * DIM];    // W1^T, tf32 bits
__device__ float g_w2t[DIM * DIM];    // W2^T, tf32 bits

__device__ __forceinline__ uint32_t f2tf32(float f) {
    uint32_t r;
    asm("cvt.rna.tf32.f32 %0, %1;" : "=r"(r) : "f"(f));
    return r;
}

// ---------------------------------------------------------------------------
// Prep: flag+degree init
// ---------------------------------------------------------------------------
__global__ void init_kernel() {
    int i = blockIdx.x * blockDim.x + threadIdx.x;
    if (i == 0) g_is_i32 = 0;
    if (i < NNODES) g_deg[i] = 1;  // self-loop
}

__global__ void dtype_sniff_kernel(const int* __restrict__ ei32) {
    int i = blockIdx.x * blockDim.x + threadIdx.x;  // 0 .. E-1
    int acc = 0;
    if (i < NEDGES) acc = ei32[2 * i + 1];
#pragma unroll
    for (int o = 16; o > 0; o >>= 1) acc |= __shfl_xor_sync(0xffffffffu, acc, o);
    if ((threadIdx.x & 31) == 0 && acc != 0) atomicOr(&g_is_i32, 1);
}

// convert edge index to int32 AND count in-degree in one pass
__global__ void convert_count_kernel(const void* __restrict__ ei) {
    int i = blockIdx.x * blockDim.x + threadIdx.x;  // 0 .. 2E-1
    if (i >= 2 * NEDGES) return;
    int v;
    if (g_is_i32) v = ((const int*)ei)[i];
    else          v = (int)((const long long*)ei)[i];
    if (i < NEDGES) {
        g_src[i] = v;
    } else {
        g_dst[i - NEDGES] = v;
        atomicAdd(&g_deg[v], 1);
    }
}

__global__ void dinv_kernel() {
    int i = blockIdx.x * blockDim.x + threadIdx.x;
    if (i < NNODES) g_dinv[i] = rsqrtf((float)g_deg[i]);
}

// X -> tf32 bits into g_a (layer-1 GEMM A operand), RNA rounding
__global__ void xconv_kernel(const float* __restrict__ X) {
    int idx = blockIdx.x * blockDim.x + threadIdx.x;
    if (idx >= NNODES * (DIM / 4)) return;
    float4 v = ((const float4*)X)[idx];
    uint4 t = make_uint4(f2tf32(v.x), f2tf32(v.y), f2tf32(v.z), f2tf32(v.w));
    ((uint4*)g_a)[idx] = t;
}

// ---------------------------------------------------------------------------
// Exclusive prefix scan of in-degree (deg-1) -> rowptr, cursor. 1 block.
// ---------------------------------------------------------------------------
#define SCAN_T 1024
__global__ void scan_kernel() {
    __shared__ int sums[SCAN_T];
    const int CH = (NNODES + SCAN_T - 1) / SCAN_T;  // 20
    int t = threadIdx.x;
    int base = t * CH;
    int local = 0;
#pragma unroll
    for (int i = 0; i < CH; i++) {
        int idx = base + i;
        if (idx < NNODES) local += g_deg[idx] - 1;
    }
    sums[t] = local;
    __syncthreads();
    for (int o = 1; o < SCAN_T; o <<= 1) {
        int v = (t >= o) ? sums[t - o] : 0;
        __syncthreads();
        sums[t] += v;
        __syncthreads();
    }
    int run = (t > 0) ? sums[t - 1] : 0;
#pragma unroll
    for (int i = 0; i < CH; i++) {
        int idx = base + i;
        if (idx < NNODES) {
            g_rowptr[idx] = run;
            g_cursor[idx] = run;
            run += g_deg[idx] - 1;
        }
    }
    if (t == SCAN_T - 1) g_rowptr[NNODES] = sums[SCAN_T - 1];
}

__global__ void scatter_kernel() {
    int e = blockIdx.x * blockDim.x + threadIdx.x;
    if (e >= NEDGES) return;
    int s = g_src[e];
    int d = g_dst[e];
    int pos = atomicAdd(&g_cursor[d], 1);
    g_csr_src[pos] = s;
    g_csr_w[pos] = g_dinv[s] * g_dinv[d];
}

// ---------------------------------------------------------------------------
// Transpose 512x512 W -> Wt with tf32 pre-conversion. blockIdx.z: 0=W1, 1=W2
// ---------------------------------------------------------------------------
__global__ void transpose512_kernel(const float* __restrict__ W1,
                                    const float* __restrict__ W2) {
    __shared__ float t[32][33];
    const float* W = blockIdx.z ? W2 : W1;
    float* o = blockIdx.z ? g_w2t : g_w1t;
    int bx = blockIdx.x * 32, by = blockIdx.y * 32;
    t[threadIdx.y][threadIdx.x] = W[(by + threadIdx.y) * DIM + bx + threadIdx.x];
    __syncthreads();
    o[(bx + threadIdx.y) * DIM + by + threadIdx.x] =
        __uint_as_float(f2tf32(t[threadIdx.x][threadIdx.y]));
}

// ---------------------------------------------------------------------------
// Tensor-core GEMM, cp.async double-buffered, operands pre-converted tf32:
//   g_h[M,512] = g_a[M,512] @ Wt^T   (Wt = g_w1t for MODE 0, g_w2t for MODE 1)
// CTA 128x128, BK=32, 256 threads = 8 warps (4 M x 2 N), warp tile 32x64.
// ---------------------------------------------------------------------------
#define SMS 36                        // smem row stride (32 + 4 pad)
#define SM_BUF (128 * SMS)            // words per tile buffer
#define GEMM_SMEM_BYTES (4 * SM_BUF * 4)  // [A0 B0 A1 B1]

__device__ __forceinline__ void cp16(uint32_t dst, const void* src) {
    asm volatile("cp.async.cg.shared.global [%0], [%1], 16;"
                 :: "r"(dst), "l"(src));
}

__device__ __forceinline__ void mma_ks(const uint32_t* __restrict__ As_,
                                       const uint32_t* __restrict__ Bs_,
                                       float (&acc)[2][8][4],
                                       int k0, int wm, int wn, int gq, int tq) {
    uint32_t af[2][4], bf[8][2];
#pragma unroll
    for (int mt = 0; mt < 2; mt++) {
        int r = wm + mt * 16 + gq;
        af[mt][0] = As_[r * SMS + k0 + tq];
        af[mt][1] = As_[(r + 8) * SMS + k0 + tq];
        af[mt][2] = As_[r * SMS + k0 + tq + 4];
        af[mt][3] = As_[(r + 8) * SMS + k0 + tq + 4];
    }
#pragma unroll
    for (int nt = 0; nt < 8; nt++) {
        int n = wn + nt * 8 + gq;
        bf[nt][0] = Bs_[n * SMS + k0 + tq];
        bf[nt][1] = Bs_[n * SMS + k0 + tq + 4];
    }
#pragma unroll
    for (int mt = 0; mt < 2; mt++)
#pragma unroll
        for (int nt = 0; nt < 8; nt++) {
            asm volatile(
                "mma.sync.aligned.m16n8k8.row.col.f32.tf32.tf32.f32 "
                "{%0,%1,%2,%3}, {%4,%5,%6,%7}, {%8,%9}, {%0,%1,%2,%3};"
                : "+f"(acc[mt][nt][0]), "+f"(acc[mt][nt][1]),
                  "+f"(acc[mt][nt][2]), "+f"(acc[mt][nt][3])
                : "r"(af[mt][0]), "r"(af[mt][1]),
                  "r"(af[mt][2]), "r"(af[mt][3]),
                  "r"(bf[nt][0]), "r"(bf[nt][1]));
        }
}

template <int MODE>
__global__ void __launch_bounds__(256, 2)
mma_gemm_kernel() {
    extern __shared__ uint32_t smem[];  // [A0 | B0 | A1 | B1]

    const float* A  = g_a;                       // tf32 bits
    const float* Bt = MODE ? g_w2t : g_w1t;      // tf32 bits

    int tid = threadIdx.x, wid = tid >> 5, lane = tid & 31;
    int row0 = blockIdx.y * 128;
    int col0 = blockIdx.x * 128;
    int wm = (wid & 3) * 32;
    int wn = (wid >> 2) * 64;
    int gq = lane >> 2;
    int tq = lane & 3;

    uint32_t sbase = (uint32_t)__cvta_generic_to_shared(smem);

    // per-thread fixed load slots: 4 x 16B for A, 4 x 16B for B
    int lr[4], lc[4], lgrow[4];
#pragma unroll
    for (int i = 0; i < 4; i++) {
        int idx = tid + 256 * i;
        lr[i] = idx >> 3;
        lc[i] = (idx & 7) * 4;
        int grow = row0 + lr[i];
        lgrow[i] = (grow < NNODES) ? grow : (NNODES - 1);  // clamp: rows >= N never stored
    }

    float acc[2][8][4];
#pragma unroll
    for (int mt = 0; mt < 2; mt++)
#pragma unroll
        for (int nt = 0; nt < 8; nt++)
#pragma unroll
            for (int j = 0; j < 4; j++) acc[mt][nt][j] = 0.f;

    // prologue: issue chunk 0
    {
        uint32_t abuf = sbase, bbuf = sbase + SM_BUF * 4;
#pragma unroll
        for (int i = 0; i < 4; i++) {
            cp16(abuf + (uint32_t)(lr[i] * SMS + lc[i]) * 4, &A[(size_t)lgrow[i] * DIM + lc[i]]);
            cp16(bbuf + (uint32_t)(lr[i] * SMS + lc[i]) * 4, &Bt[(size_t)(col0 + lr[i]) * DIM + lc[i]]);
        }
        asm volatile("cp.async.commit_group;" ::: "memory");
    }

    for (int c = 0; c < 16; c++) {
        if (c < 15) {
            int kn = (c + 1) * 32;
            uint32_t abuf = sbase + ((c + 1) & 1) * 2 * SM_BUF * 4;
            uint32_t bbuf = abuf + SM_BUF * 4;
#pragma unroll
            for (int i = 0; i < 4; i++) {
                cp16(abuf + (uint32_t)(lr[i] * SMS + lc[i]) * 4,
                     &A[(size_t)lgrow[i] * DIM + kn + lc[i]]);
                cp16(bbuf + (uint32_t)(lr[i] * SMS + lc[i]) * 4,
                     &Bt[(size_t)(col0 + lr[i]) * DIM + kn + lc[i]]);
            }
            asm volatile("cp.async.commit_group;" ::: "memory");
            asm volatile("cp.async.wait_group 1;" ::: "memory");
        } else {
            asm volatile("cp.async.wait_group 0;" ::: "memory");
        }
        __syncthreads();

        const uint32_t* curA = smem + (c & 1) * 2 * SM_BUF;
        const uint32_t* curB = curA + SM_BUF;
        mma_ks(curA, curB, acc, 0,  wm, wn, gq, tq);
        mma_ks(curA, curB, acc, 8,  wm, wn, gq, tq);
        mma_ks(curA, curB, acc, 16, wm, wn, gq, tq);
        mma_ks(curA, curB, acc, 24, wm, wn, gq, tq);
        __syncthreads();
    }

    // ---- epilogue: fragments -> g_h ----
#pragma unroll
    for (int mt = 0; mt < 2; mt++) {
        int r0 = row0 + wm + mt * 16 + gq;
#pragma unroll
        for (int nt = 0; nt < 8; nt++) {
            int cc = col0 + wn + nt * 8 + tq * 2;
            if (r0 < NNODES)
                *(float2*)&g_h[(size_t)r0 * DIM + cc] =
                    make_float2(acc[mt][nt][0], acc[mt][nt][1]);
            if (r0 + 8 < NNODES)
                *(float2*)&g_h[(size_t)(r0 + 8) * DIM + cc] =
                    make_float2(acc[mt][nt][2], acc[mt][nt][3]);
        }
    }
}

// ---------------------------------------------------------------------------
// Shared edge-accumulate body (fp32 exact):
//   acc = dinv[d]^2 * h[d,:] + sum_{e: dst=d} w_e * h[src_e,:]   (one float4 col)
// ---------------------------------------------------------------------------
__device__ __forceinline__ float4 agg_row(int d, int t) {
    const float4* __restrict__ h4 = (const float4*)g_h;
    float dv = g_dinv[d];
    float4 acc = h4[(size_t)d * 128 + t];
    float ws = dv * dv;
    acc.x *= ws; acc.y *= ws; acc.z *= ws; acc.w *= ws;

    int j   = g_rowptr[d];
    int end = g_rowptr[d + 1];
    for (; j + 4 <= end; j += 4) {
        int   s0 = g_csr_src[j],     s1 = g_csr_src[j + 1];
        int   s2 = g_csr_src[j + 2], s3 = g_csr_src[j + 3];
        float w0 = g_csr_w[j],       w1 = g_csr_w[j + 1];
        float w2 = g_csr_w[j + 2],   w3 = g_csr_w[j + 3];
        float4 v0 = h4[(size_t)s0 * 128 + t];
        float4 v1 = h4[(size_t)s1 * 128 + t];
        float4 v2 = h4[(size_t)s2 * 128 + t];
        float4 v3 = h4[(size_t)s3 * 128 + t];
        acc.x += v0.x * w0 + v1.x * w1 + v2.x * w2 + v3.x * w3;
        acc.y += v0.y * w0 + v1.y * w1 + v2.y * w2 + v3.y * w3;
        acc.z += v0.z * w0 + v1.z * w1 + v2.z * w2 + v3.z * w3;
        acc.w += v0.w * w0 + v1.w * w1 + v2.w * w2 + v3.w * w3;
    }
    for (; j < end; j++) {
        int   s = g_csr_src[j];
        float w = g_csr_w[j];
        float4 v = h4[(size_t)s * 128 + t];
        acc.x += v.x * w; acc.y += v.y * w;
        acc.z += v.z * w; acc.w += v.w * w;
    }
    return acc;
}

// Layer 1: agg + bias + relu + tf32(RNA) -> g_a (layer-2 GEMM A operand)
__global__ void __launch_bounds__(128)
agg_csr_kernel(const float* __restrict__ b1) {
    int d = blockIdx.x;
    int t = threadIdx.x;
    float4 acc = agg_row(d, t);
    float4 bb = ((const float4*)b1)[t];
    uint4 o = make_uint4(f2tf32(fmaxf(acc.x + bb.x, 0.f)),
                         f2tf32(fmaxf(acc.y + bb.y, 0.f)),
                         f2tf32(fmaxf(acc.z + bb.z, 0.f)),
                         f2tf32(fmaxf(acc.w + bb.w, 0.f)));
    ((uint4*)g_a)[(size_t)d * 128 + t] = o;
}

// Layer 2: aggregation fused with bias + relu + global max pool.
#define NPB 8
__global__ void __launch_bounds__(128)
agg_pool_kernel(const float* __restrict__ b2, float* __restrict__ out) {
    int t = threadIdx.x;
    int d0 = blockIdx.x * NPB;
    float4 bb = ((const float4*)b2)[t];
    float4 mx = make_float4(0.f, 0.f, 0.f, 0.f);
#pragma unroll
    for (int n = 0; n < NPB; n++) {
        float4 acc = agg_row(d0 + n, t);
        mx.x = fmaxf(mx.x, acc.x + bb.x);
        mx.y = fmaxf(mx.y, acc.y + bb.y);
        mx.z = fmaxf(mx.z, acc.z + bb.z);
        mx.w = fmaxf(mx.w, acc.w + bb.w);
    }
    mx.x = fmaxf(mx.x, 0.f); mx.y = fmaxf(mx.y, 0.f);
    mx.z = fmaxf(mx.z, 0.f); mx.w = fmaxf(mx.w, 0.f);
    int* o = (int*)out;
    atomicMax(o + 4 * t + 0, __float_as_int(mx.x));
    atomicMax(o + 4 * t + 1, __float_as_int(mx.y));
    atomicMax(o + 4 * t + 2, __float_as_int(mx.z));
    atomicMax(o + 4 * t + 3, __float_as_int(mx.w));
}

__global__ void out_init_kernel(float* out) {
    int j = threadIdx.x;
    if (j < DIM) out[j] = 0.0f;
}

// ---------------------------------------------------------------------------
extern "C" void kernel_launch(void* const* d_in, const int* in_sizes, int n_in,
                              void* d_out, int out_size) {
    const float* X  = (const float*)d_in[0];
    const void*  ei = d_in[1];
    // d_in[2] = edge_attr (unused by GCNConv)
    const float* W1 = (const float*)d_in[3];
    const float* b1 = (const float*)d_in[4];
    const float* W2 = (const float*)d_in[5];
    const float* b2 = (const float*)d_in[6];
    float* out = (float*)d_out;

    cudaFuncSetAttribute(mma_gemm_kernel<0>,
                         cudaFuncAttributeMaxDynamicSharedMemorySize, GEMM_SMEM_BYTES);
    cudaFuncSetAttribute(mma_gemm_kernel<1>,
                         cudaFuncAttributeMaxDynamicSharedMemorySize, GEMM_SMEM_BYTES);

    // ---- prep ----
    init_kernel<<<(NNODES + 255) / 256, 256>>>();
    dtype_sniff_kernel<<<(NEDGES + 255) / 256, 256>>>((const int*)ei);
    convert_count_kernel<<<(2 * NEDGES + 255) / 256, 256>>>(ei);
    dinv_kernel<<<(NNODES + 255) / 256, 256>>>();
    scan_kernel<<<1, SCAN_T>>>();
    scatter_kernel<<<(NEDGES + 255) / 256, 256>>>();
    dim3 tgrid(16, 16, 2), tblk(32, 32);
    transpose512_kernel<<<tgrid, tblk>>>(W1, W2);
    xconv_kernel<<<(NNODES * (DIM / 4) + 255) / 256, 256>>>(X);
    out_init_kernel<<<1, DIM>>>(out);

    dim3 gemm_grid(DIM / 128, (NNODES + 127) / 128);  // (4, 157)

    // ---- layer 1: h = X @ W1 ; a = tf32(relu(A_norm h + b1)) ----
    mma_gemm_kernel<0><<<gemm_grid, 256, GEMM_SMEM_BYTES>>>();
    agg_csr_kernel<<<NNODES, 128>>>(b1);

    // ---- layer 2: h = a @ W2 ; fused agg + bias + relu + max pool ----
    mma_gemm_kernel<1><<<gemm_grid, 256, GEMM_SMEM_BYTES>>>();
    agg_pool_kernel<<<NNODES / NPB, 128>>>(b2, out);
}